// round 1
// baseline (speedup 1.0000x reference)
#include <cuda_runtime.h>
#include <cstddef>

#define BATCHN 128
#define SEQN   2048
#define FEATN  64
#define UNITSN 64
#define GATESN 256
#define OUTDN  6

__device__ __forceinline__ float rcp_f(float x) {
    float r; asm("rcp.approx.f32 %0, %1;" : "=f"(r) : "f"(x)); return r;
}
__device__ __forceinline__ float ex2_f(float x) {
    float r; asm("ex2.approx.f32 %0, %1;" : "=f"(r) : "f"(x)); return r;
}

// z -> activated gate, branchless via per-thread constants:
//   sigmoid(z) = 1/(1+exp2(-z*log2e))            (gates i,f,o)
//   tanh(z)    = 2/(1+exp2(-2z*log2e)) - 1       (gate g)
__global__ void __launch_bounds__(256, 1)
lstm_scan_kernel(const float* __restrict__ x,
                 const float* __restrict__ W0, const float* __restrict__ U0,
                 const float* __restrict__ b0,
                 const float* __restrict__ W1, const float* __restrict__ U1,
                 const float* __restrict__ b1,
                 const float* __restrict__ Wf, const float* __restrict__ bf,
                 const float* __restrict__ Wo, const float* __restrict__ bo,
                 float* __restrict__ out)
{
    extern __shared__ float sm[];
    float* W0s = sm;                    // 64*256 floats, gate-interleaved columns
    float* U0s = W0s + FEATN * GATESN;  // 64*256
    float* h0s = U0s + UNITSN * GATESN; // 2*64 (double buffered)
    float* h1s = h0s + 2 * UNITSN;      // 2*64
    float* h2s = h1s + 2 * UNITSN;      // 2*64
    float* xs  = h2s + 2 * UNITSN;      // 2*64
    float* fs  = xs  + 2 * FEATN;       // 64

    const int b   = blockIdx.x;
    const int tid = threadIdx.x;
    const int w   = tid >> 5;
    const int l   = tid & 31;
    const int uin = l & 7;           // unit-within-warp
    const int g   = l >> 3;          // gate 0..3  (i,f,g,o)
    const int u   = (w << 3) | uin;  // unit 0..63
    const int j   = (g << 6) | u;    // logical gate column 0..255
    const int p   = (u << 2) | g;    // swizzled (gate-interleaved) column -> conflict-free banks

    // Stage W0/U0 into smem at swizzled column positions (coalesced global reads)
    for (int i = tid; i < FEATN * GATESN; i += 256) {
        int k  = i >> 8;
        int jj = i & 255;
        int pp = ((jj & 63) << 2) | (jj >> 6);
        W0s[(k << 8) + pp] = W0[i];
        U0s[(k << 8) + pp] = U0[i];
    }

    // Layer-1/2 weights (shared by both upper layers) live in registers: this
    // thread's column of W1 and U1.
    float w1r[UNITSN], u1r[UNITSN];
#pragma unroll
    for (int k = 0; k < UNITSN; k++) {
        w1r[k] = W1[(k << 8) + j];
        u1r[k] = U1[(k << 8) + j];
    }
    const float b0r = b0[j];
    const float b1r = b1[j];

    if (tid < UNITSN) {
        h0s[tid] = 0.f; h0s[UNITSN + tid] = 0.f;
        h1s[tid] = 0.f; h1s[UNITSN + tid] = 0.f;
        h2s[tid] = 0.f; h2s[UNITSN + tid] = 0.f;
    }
    const float* xb = x + (size_t)b * SEQN * FEATN;
    if (tid < FEATN) xs[tid] = xb[tid];

    // Per-thread activation constants (gate 2 is the tanh candidate gate)
    const float kpre = (g == 2) ? -2.8853900817779268f : -1.4426950408889634f;
    const float kmul = (g == 2) ?  2.0f : 1.0f;
    const float kadd = (g == 2) ? -1.0f : 0.0f;
    const unsigned FULL = 0xffffffffu;

    float c0 = 0.f, c1 = 0.f, c2 = 0.f;  // cell state for unit u, replicated x4 lanes
    __syncthreads();

    int cur = 0;
    for (int t = 0; t < SEQN; t++) {
        const int nxt = cur ^ 1;

        // Prefetch next timestep's x early; lands in smem before final sync.
        float xn = 0.f;
        if (tid < FEATN && t + 1 < SEQN)
            xn = __ldg(xb + (size_t)(t + 1) * FEATN + tid);

        // ---------------- layer 0: z = x*W0 + h0*U0 + b0 ----------------
        float a0 = b0r, a1 = 0.f, a2 = 0.f, a3 = 0.f;
#pragma unroll
        for (int k = 0; k < 64; k += 4) {
            float4 xv = *reinterpret_cast<const float4*>(xs  + cur * FEATN  + k);
            float4 hv = *reinterpret_cast<const float4*>(h0s + cur * UNITSN + k);
            a0 = fmaf(xv.x, W0s[(k + 0) * GATESN + p], a0);
            a1 = fmaf(xv.y, W0s[(k + 1) * GATESN + p], a1);
            a2 = fmaf(xv.z, W0s[(k + 2) * GATESN + p], a2);
            a3 = fmaf(xv.w, W0s[(k + 3) * GATESN + p], a3);
            a0 = fmaf(hv.x, U0s[(k + 0) * GATESN + p], a0);
            a1 = fmaf(hv.y, U0s[(k + 1) * GATESN + p], a1);
            a2 = fmaf(hv.z, U0s[(k + 2) * GATESN + p], a2);
            a3 = fmaf(hv.w, U0s[(k + 3) * GATESN + p], a3);
        }
        {
            float z   = (a0 + a1) + (a2 + a3);
            float act = fmaf(rcp_f(1.0f + ex2_f(z * kpre)), kmul, kadd);
            float vi = __shfl_sync(FULL, act, uin);
            float vf = __shfl_sync(FULL, act, uin + 8);
            float vg = __shfl_sync(FULL, act, uin + 16);
            float vo = __shfl_sync(FULL, act, uin + 24);
            c0 = fmaf(vf, c0, vi * vg);
            float e  = ex2_f(c0 * -2.8853900817779268f);
            float hn = vo * fmaf(2.0f, rcp_f(1.0f + e), -1.0f);
            if (l < 8) h0s[nxt * UNITSN + u] = hn;
        }
        __syncthreads();

        // ---------------- layer 1: z = h0_new*W1 + h1*U1 + b1 ----------------
        a0 = b1r; a1 = 0.f; a2 = 0.f; a3 = 0.f;
#pragma unroll
        for (int k = 0; k < 64; k += 4) {
            float4 iv = *reinterpret_cast<const float4*>(h0s + nxt * UNITSN + k);
            float4 hv = *reinterpret_cast<const float4*>(h1s + cur * UNITSN + k);
            a0 = fmaf(iv.x, w1r[k + 0], a0);
            a1 = fmaf(iv.y, w1r[k + 1], a1);
            a2 = fmaf(iv.z, w1r[k + 2], a2);
            a3 = fmaf(iv.w, w1r[k + 3], a3);
            a0 = fmaf(hv.x, u1r[k + 0], a0);
            a1 = fmaf(hv.y, u1r[k + 1], a1);
            a2 = fmaf(hv.z, u1r[k + 2], a2);
            a3 = fmaf(hv.w, u1r[k + 3], a3);
        }
        {
            float z   = (a0 + a1) + (a2 + a3);
            float act = fmaf(rcp_f(1.0f + ex2_f(z * kpre)), kmul, kadd);
            float vi = __shfl_sync(FULL, act, uin);
            float vf = __shfl_sync(FULL, act, uin + 8);
            float vg = __shfl_sync(FULL, act, uin + 16);
            float vo = __shfl_sync(FULL, act, uin + 24);
            c1 = fmaf(vf, c1, vi * vg);
            float e  = ex2_f(c1 * -2.8853900817779268f);
            float hn = vo * fmaf(2.0f, rcp_f(1.0f + e), -1.0f);
            if (l < 8) h1s[nxt * UNITSN + u] = hn;
        }
        __syncthreads();

        // ------- layer 2: z = h1_new*W1 + h2*U1 + b1 (weights shared) -------
        a0 = b1r; a1 = 0.f; a2 = 0.f; a3 = 0.f;
#pragma unroll
        for (int k = 0; k < 64; k += 4) {
            float4 iv = *reinterpret_cast<const float4*>(h1s + nxt * UNITSN + k);
            float4 hv = *reinterpret_cast<const float4*>(h2s + cur * UNITSN + k);
            a0 = fmaf(iv.x, w1r[k + 0], a0);
            a1 = fmaf(iv.y, w1r[k + 1], a1);
            a2 = fmaf(iv.z, w1r[k + 2], a2);
            a3 = fmaf(iv.w, w1r[k + 3], a3);
            a0 = fmaf(hv.x, u1r[k + 0], a0);
            a1 = fmaf(hv.y, u1r[k + 1], a1);
            a2 = fmaf(hv.z, u1r[k + 2], a2);
            a3 = fmaf(hv.w, u1r[k + 3], a3);
        }
        {
            float z   = (a0 + a1) + (a2 + a3);
            float act = fmaf(rcp_f(1.0f + ex2_f(z * kpre)), kmul, kadd);
            float vi = __shfl_sync(FULL, act, uin);
            float vf = __shfl_sync(FULL, act, uin + 8);
            float vg = __shfl_sync(FULL, act, uin + 16);
            float vo = __shfl_sync(FULL, act, uin + 24);
            c2 = fmaf(vf, c2, vi * vg);
            float e  = ex2_f(c2 * -2.8853900817779268f);
            float hn = vo * fmaf(2.0f, rcp_f(1.0f + e), -1.0f);
            if (l < 8) h2s[nxt * UNITSN + u] = hn;
        }
        if (tid < FEATN) xs[nxt * FEATN + tid] = xn;
        __syncthreads();

        cur = nxt;
    }

    // ---------------- dense head: relu(h2*Wf+bf) * Wo + bo ----------------
    if (tid < UNITSN) {
        float a = bf[tid];
#pragma unroll 8
        for (int k = 0; k < UNITSN; k++)
            a = fmaf(h2s[cur * UNITSN + k], Wf[k * 64 + tid], a);
        fs[tid] = fmaxf(a, 0.f);
    }
    __syncthreads();
    if (tid < OUTDN) {
        float a = bo[tid];
#pragma unroll 8
        for (int k = 0; k < UNITSN; k++)
            a = fmaf(fs[k], Wo[k * OUTDN + tid], a);
        out[b * OUTDN + tid] = a;
    }
}

extern "C" void kernel_launch(void* const* d_in, const int* in_sizes, int n_in,
                              void* d_out, int out_size)
{
    (void)in_sizes; (void)n_in; (void)out_size;
    const float* x  = (const float*)d_in[0];
    const float* W0 = (const float*)d_in[1];
    const float* U0 = (const float*)d_in[2];
    const float* b0 = (const float*)d_in[3];
    const float* W1 = (const float*)d_in[4];
    const float* U1 = (const float*)d_in[5];
    const float* b1 = (const float*)d_in[6];
    const float* Wf = (const float*)d_in[7];
    const float* bf = (const float*)d_in[8];
    const float* Wo = (const float*)d_in[9];
    const float* bo = (const float*)d_in[10];
    float* out = (float*)d_out;

    const size_t smem_bytes =
        (size_t)(2 * FEATN * GATESN + 6 * UNITSN + 2 * FEATN + UNITSN) * sizeof(float);
    cudaFuncSetAttribute(lstm_scan_kernel,
                         cudaFuncAttributeMaxDynamicSharedMemorySize,
                         (int)smem_bytes);
    lstm_scan_kernel<<<BATCHN, 256, smem_bytes>>>(x, W0, U0, b0, W1, U1, b1,
                                                  Wf, bf, Wo, bo, out);
}